// round 13
// baseline (speedup 1.0000x reference)
#include <cuda_runtime.h>
#include <cuda_fp16.h>
#include <math.h>
#include <stdint.h>

// ---------------- problem constants ----------------------------------------
#define MAXN 100000
#define MAXE 1600000
#define H 128
#define NF 133
#define K0P 144          // layer-0 K padded to multiple of 16

// ---------------- static scratch: referenced ONLY inside device code --------
__device__ float  g_dinv[MAXN];
__device__ int    g_deg[MAXN];
__device__ int    g_rowptr[MAXN + 1];
__device__ int    g_cursor[MAXN];
__device__ int    g_col[MAXE];
__device__ __half g_hs[(size_t)MAXN * H];     // dinv-scaled GEMM output (fp16)
__device__ __half g_act[(size_t)MAXN * H];    // activations (fp16)
__device__ __half g_xh[(size_t)MAXN * K0P];   // x fp16, padded
__device__ __half g_w0T[H * K0P];             // W0^T [n][k] fp16, padded
__device__ __half g_wT[3][H * H];             // W1..3^T [n][k] fp16
__device__ int    g_bsum[512];
__device__ int    g_boff[512];

// ---------------- helpers ----------------------------------------------------
__device__ __forceinline__ void mma_f16(float c[4], const uint32_t a[4],
                                        const uint32_t b[2]) {
    asm volatile(
        "mma.sync.aligned.m16n8k16.row.col.f32.f16.f16.f32 "
        "{%0,%1,%2,%3}, {%4,%5,%6,%7}, {%8,%9}, {%0,%1,%2,%3};"
        : "+f"(c[0]), "+f"(c[1]), "+f"(c[2]), "+f"(c[3])
        : "r"(a[0]), "r"(a[1]), "r"(a[2]), "r"(a[3]), "r"(b[0]), "r"(b[1]));
}

__device__ __forceinline__ void cp16(uint32_t dst, const void* src, bool pred) {
    int sz = pred ? 16 : 0;
    asm volatile("cp.async.ca.shared.global [%0], [%1], 16, %2;"
                 :: "r"(dst), "l"(src), "r"(sz));
}
__device__ __forceinline__ void cp_commit() {
    asm volatile("cp.async.commit_group;");
}
template <int NN>
__device__ __forceinline__ void cp_wait() {
    asm volatile("cp.async.wait_group %0;" :: "n"(NN));
}

__device__ __forceinline__ float tanh_ap(float x) {
    float y;
    asm("tanh.approx.f32 %0, %1;" : "=f"(y) : "f"(x));
    return y;
}

__device__ __forceinline__ void acc_h8(float acc[8], uint4 u) {
    __half2* h = (__half2*)&u;
#pragma unroll
    for (int i = 0; i < 4; i++) {
        float2 f = __half22float2(h[i]);
        acc[2 * i]     += f.x;
        acc[2 * i + 1] += f.y;
    }
}

// ---------------- prep: convert inputs/weights to fp16 (+ zero deg) ---------
__global__ void k_prep_x(const float* __restrict__ x, int n) {
    int idx = blockIdx.x * blockDim.x + threadIdx.x;
    if (idx < n) g_deg[idx] = 0;                 // fused deg zeroing
    if (idx >= n * K0P) return;
    int row = idx / K0P, col = idx - row * K0P;
    float v = (col < NF) ? x[(size_t)row * NF + col] : 0.0f;
    g_xh[idx] = __float2half_rn(v);
}

// W stored transposed [n][k] so the B fragment packs 2 k-adjacent halves.
__global__ void k_prep_w(const float* __restrict__ W0, const float* __restrict__ W1,
                         const float* __restrict__ W2, const float* __restrict__ W3) {
    int idx = blockIdx.x * blockDim.x + threadIdx.x;
    if (idx < H * K0P) {
        int nn = idx / K0P, k = idx - nn * K0P;
        float v = (k < NF) ? W0[(size_t)k * H + nn] : 0.0f;
        g_w0T[idx] = __float2half_rn(v);
    } else if (idx < H * K0P + 3 * H * H) {
        int r = idx - H * K0P;
        int l = r / (H * H);
        int o = r - l * (H * H);
        int nn = o >> 7, k = o & 127;
        const float* W = (l == 0) ? W1 : (l == 1) ? W2 : W3;
        g_wT[l][o] = __float2half_rn(W[(size_t)k * H + nn]);
    }
}

// ---------------- preprocessing kernels -------------------------------------
// vectorized: 4 edges per thread via int4
__global__ void k_count(const int* __restrict__ ei, int E, int n) {
    int t = blockIdx.x * blockDim.x + threadIdx.x;
    int E4 = E >> 2;
    if (((E & 3) == 0)) {
        if (t < E4) {
            int4 d = ((const int4*)(ei + E))[t];
            if ((unsigned)d.x < (unsigned)n) atomicAdd(&g_deg[d.x], 1);
            if ((unsigned)d.y < (unsigned)n) atomicAdd(&g_deg[d.y], 1);
            if ((unsigned)d.z < (unsigned)n) atomicAdd(&g_deg[d.z], 1);
            if ((unsigned)d.w < (unsigned)n) atomicAdd(&g_deg[d.w], 1);
        }
    } else {
        int e = t;
        if (e < E) {
            int d = ei[E + e];
            if ((unsigned)d < (unsigned)n) atomicAdd(&g_deg[d], 1);
        }
    }
}

__global__ void k_partial(int n) {
    __shared__ int s[512];
    int t = threadIdx.x;
    int i = blockIdx.x * 512 + t;
    s[t] = (i < n) ? g_deg[i] : 0;
    __syncthreads();
    for (int off = 256; off > 0; off >>= 1) {
        if (t < off) s[t] += s[t + off];
        __syncthreads();
    }
    if (t == 0) g_bsum[blockIdx.x] = s[0];
}

__global__ void k_scanb(int nb, int n) {
    __shared__ int s[512];
    int t = threadIdx.x;
    int v = (t < nb) ? g_bsum[t] : 0;
    s[t] = v;
    __syncthreads();
    for (int off = 1; off < 512; off <<= 1) {
        int x = (t >= off) ? s[t - off] : 0;
        __syncthreads();
        s[t] += x;
        __syncthreads();
    }
    if (t < nb) g_boff[t] = s[t] - v;
    if (t == 511) g_rowptr[n] = s[511];
}

__global__ void k_rowptr(int n) {
    __shared__ int s[512];
    int t = threadIdx.x;
    int i = blockIdx.x * 512 + t;
    int v = (i < n) ? g_deg[i] : 0;
    s[t] = v;
    __syncthreads();
    for (int off = 1; off < 512; off <<= 1) {
        int x = (t >= off) ? s[t - off] : 0;
        __syncthreads();
        s[t] += x;
        __syncthreads();
    }
    if (i < n) {
        int rp = g_boff[blockIdx.x] + s[t] - v;
        g_rowptr[i] = rp;
        g_cursor[i] = rp;
        g_dinv[i] = rsqrtf((float)v + 1.0f);
    }
}

// vectorized fill: 4 edges per thread
__global__ void k_fill(const int* __restrict__ ei, int E, int n) {
    int t = blockIdx.x * blockDim.x + threadIdx.x;
    int E4 = E >> 2;
    if (((E & 3) == 0)) {
        if (t < E4) {
            int4 sv = ((const int4*)ei)[t];
            int4 dv = ((const int4*)(ei + E))[t];
            if ((unsigned)dv.x < (unsigned)n && (unsigned)sv.x < (unsigned)n) {
                int pos = atomicAdd(&g_cursor[dv.x], 1);
                if ((unsigned)pos < (unsigned)E) g_col[pos] = sv.x;
            }
            if ((unsigned)dv.y < (unsigned)n && (unsigned)sv.y < (unsigned)n) {
                int pos = atomicAdd(&g_cursor[dv.y], 1);
                if ((unsigned)pos < (unsigned)E) g_col[pos] = sv.y;
            }
            if ((unsigned)dv.z < (unsigned)n && (unsigned)sv.z < (unsigned)n) {
                int pos = atomicAdd(&g_cursor[dv.z], 1);
                if ((unsigned)pos < (unsigned)E) g_col[pos] = sv.z;
            }
            if ((unsigned)dv.w < (unsigned)n && (unsigned)sv.w < (unsigned)n) {
                int pos = atomicAdd(&g_cursor[dv.w], 1);
                if ((unsigned)pos < (unsigned)E) g_col[pos] = sv.w;
            }
        }
    } else {
        int e = t;
        if (e < E) {
            int srcv = ei[e];
            int d    = ei[E + e];
            if ((unsigned)d < (unsigned)n && (unsigned)srcv < (unsigned)n) {
                int pos = atomicAdd(&g_cursor[d], 1);
                if ((unsigned)pos < (unsigned)E) g_col[pos] = srcv;
            }
        }
    }
}

// ---------------- GEMM (fp16 TC, cp.async double-buffered) -------------------
// g_hs = fp16( (A[M,K] @ W[K,128]) * dinv[row] ).
// asel: 0 -> A = g_xh (stride K0P), 1 -> A = g_act (stride H).
// wsel: 0..3 selects W^T array. All symbols resolved in device code.
__global__ __launch_bounds__(256, 2)
void k_gemm_f16(int asel, int wsel, int M, int K, int SA) {
    const __half* __restrict__ A  = (asel == 0) ? g_xh : g_act;
    const __half* __restrict__ WT = (wsel == 0) ? g_w0T : g_wT[wsel - 1];
    __shared__ uint32_t As[2][128 * 8];
    __shared__ uint32_t Ws[2][128 * 8];

    const int tid  = threadIdx.x;
    const int lane = tid & 31;
    const int w    = tid >> 5;
    const int wm   = (w >> 1) * 32;
    const int wn   = (w & 1) * 64;
    const int grp  = lane >> 2;
    const int qid  = lane & 3;
    const int row0 = blockIdx.x * 128;
    const int P    = K >> 4;

    const int lrow = tid >> 1;
    const int lh   = (tid & 1) * 8;
    const int lw   = (tid & 1) * 4;

    float acc[2][8][4];
#pragma unroll
    for (int mi = 0; mi < 2; mi++)
#pragma unroll
        for (int ni = 0; ni < 8; ni++)
#pragma unroll
            for (int r = 0; r < 4; r++) acc[mi][ni][r] = 0.0f;

    auto load_panel = [&](int p, int s) {
        int k0 = p * 16;
        uint32_t ab = (uint32_t)__cvta_generic_to_shared(&As[s][0]);
        uint32_t wb = (uint32_t)__cvta_generic_to_shared(&Ws[s][0]);
        bool pa = (row0 + lrow) < M;
        const __half* sa = A + (size_t)(pa ? row0 + lrow : 0) * SA + k0 + lh;
        cp16(ab + (lrow * 8 + lw) * 4, sa, pa);
        const __half* sw = WT + (size_t)lrow * K + k0 + lh;
        cp16(wb + (lrow * 8 + lw) * 4, sw, true);
        cp_commit();
    };

    load_panel(0, 0);

    for (int p = 0; p < P; p++) {
        int s = p & 1;
        if (p + 1 < P) {
            load_panel(p + 1, s ^ 1);
            cp_wait<1>();
        } else {
            cp_wait<0>();
        }
        __syncthreads();

        const uint32_t* as = &As[s][0];
        const uint32_t* ws = &Ws[s][0];
        uint32_t afr[2][4];
#pragma unroll
        for (int mi = 0; mi < 2; mi++) {
            int r = wm + mi * 16 + grp;
            afr[mi][0] = as[r * 8 + qid];
            afr[mi][1] = as[(r + 8) * 8 + qid];
            afr[mi][2] = as[r * 8 + qid + 4];
            afr[mi][3] = as[(r + 8) * 8 + qid + 4];
        }
        uint32_t bfr[8][2];
#pragma unroll
        for (int ni = 0; ni < 8; ni++) {
            int nn = wn + ni * 8 + grp;
            bfr[ni][0] = ws[nn * 8 + qid];
            bfr[ni][1] = ws[nn * 8 + qid + 4];
        }
#pragma unroll
        for (int mi = 0; mi < 2; mi++)
#pragma unroll
            for (int ni = 0; ni < 8; ni++)
                mma_f16(acc[mi][ni], afr[mi], bfr[ni]);
        __syncthreads();
    }

#pragma unroll
    for (int mi = 0; mi < 2; mi++) {
        int r0 = row0 + wm + mi * 16 + grp;
        int r1 = r0 + 8;
        float d0 = (r0 < M) ? g_dinv[r0] : 0.0f;
        float d1 = (r1 < M) ? g_dinv[r1] : 0.0f;
#pragma unroll
        for (int ni = 0; ni < 8; ni++) {
            int c = wn + ni * 8 + qid * 2;
            if (r0 < M) {
                __half2 hv = __floats2half2_rn(acc[mi][ni][0] * d0, acc[mi][ni][1] * d0);
                *(__half2*)(g_hs + (size_t)r0 * H + c) = hv;
            }
            if (r1 < M) {
                __half2 hv = __floats2half2_rn(acc[mi][ni][2] * d1, acc[mi][ni][3] * d1);
                *(__half2*)(g_hs + (size_t)r1 * H + c) = hv;
            }
        }
    }
}

// ---------------- aggregation: HALF-WARP per node (uint4 / LDG.128) ----------
// out_i = tanh(dinv_i * (hs_i + sum_{e in row i} hs[col[e]]) + b)
__global__ __launch_bounds__(256)
void k_aggregate(const float* __restrict__ bias, float* outext, int n) {
    int hw = (blockIdx.x * blockDim.x + threadIdx.x) >> 4;   // half-warp = node
    if (hw >= n) return;
    int lane = threadIdx.x & 15;

    const uint4* __restrict__ hp = (const uint4*)g_hs;       // 16 uint4 per row

    float acc[8] = {0, 0, 0, 0, 0, 0, 0, 0};
    acc_h8(acc, hp[(size_t)hw * 16 + lane]);                 // self term

    int e = g_rowptr[hw];
    int end = g_rowptr[hw + 1];
    for (; e + 3 < end; e += 4) {
        int j0 = g_col[e],     j1 = g_col[e + 1];
        int j2 = g_col[e + 2], j3 = g_col[e + 3];
        uint4 v0 = hp[(size_t)j0 * 16 + lane];
        uint4 v1 = hp[(size_t)j1 * 16 + lane];
        uint4 v2 = hp[(size_t)j2 * 16 + lane];
        uint4 v3 = hp[(size_t)j3 * 16 + lane];
        acc_h8(acc, v0); acc_h8(acc, v1); acc_h8(acc, v2); acc_h8(acc, v3);
    }
    for (; e < end; e++) {
        acc_h8(acc, hp[(size_t)g_col[e] * 16 + lane]);
    }

    float di = g_dinv[hw];
    float4 bb0 = ((const float4*)bias)[lane * 2];
    float4 bb1 = ((const float4*)bias)[lane * 2 + 1];
    float o[8];
    o[0] = tanh_ap(di * acc[0] + bb0.x);
    o[1] = tanh_ap(di * acc[1] + bb0.y);
    o[2] = tanh_ap(di * acc[2] + bb0.z);
    o[3] = tanh_ap(di * acc[3] + bb0.w);
    o[4] = tanh_ap(di * acc[4] + bb1.x);
    o[5] = tanh_ap(di * acc[5] + bb1.y);
    o[6] = tanh_ap(di * acc[6] + bb1.z);
    o[7] = tanh_ap(di * acc[7] + bb1.w);

    if (outext) {
        float4* op = (float4*)(outext + (size_t)hw * H + lane * 8);
        op[0] = make_float4(o[0], o[1], o[2], o[3]);
        op[1] = make_float4(o[4], o[5], o[6], o[7]);
    } else {
        __half2 h0 = __floats2half2_rn(o[0], o[1]);
        __half2 h1 = __floats2half2_rn(o[2], o[3]);
        __half2 h2 = __floats2half2_rn(o[4], o[5]);
        __half2 h3 = __floats2half2_rn(o[6], o[7]);
        uint4 u;
        u.x = *(uint32_t*)&h0; u.y = *(uint32_t*)&h1;
        u.z = *(uint32_t*)&h2; u.w = *(uint32_t*)&h3;
        ((uint4*)g_act)[(size_t)hw * 16 + lane] = u;
    }
}

// ---------------- launch -----------------------------------------------------
extern "C" void kernel_launch(void* const* d_in, const int* in_sizes, int n_in,
                              void* d_out, int out_size) {
    const float* x  = (const float*)d_in[0];
    const int*   ei = (const int*)d_in[1];       // int32 (2, E)
    const float* W0 = (const float*)d_in[2];
    const float* b0 = (const float*)d_in[3];
    const float* W1 = (const float*)d_in[4];
    const float* b1 = (const float*)d_in[5];
    const float* W2 = (const float*)d_in[6];
    const float* b2 = (const float*)d_in[7];
    const float* W3 = (const float*)d_in[8];
    const float* b3 = (const float*)d_in[9];
    float* out = (float*)d_out;

    int N = in_sizes[0] / NF;
    int E = in_sizes[1] / 2;
    if (N > MAXN) N = MAXN;
    if (E > MAXE) E = MAXE;

    int nb = (N + 511) / 512;
    int ecnt = ((E & 3) == 0) ? (E >> 2) : E;

    // prep (k_prep_x also zeroes g_deg)
    k_prep_x<<<(N * K0P + 255) / 256, 256>>>(x, N);
    k_prep_w<<<(H * K0P + 3 * H * H + 255) / 256, 256>>>(W0, W1, W2, W3);

    // graph preprocessing
    k_count<<<(ecnt + 255) / 256, 256>>>(ei, E, N);
    k_partial<<<nb, 512>>>(N);
    k_scanb<<<1, 512>>>(nb, N);
    k_rowptr<<<nb, 512>>>(N);
    k_fill<<<(ecnt + 255) / 256, 256>>>(ei, E, N);

    int gemm_grid = (N + 127) / 128;
    int agg_grid  = (N + 15) / 16;   // 16 half-warps per 256-thread block

    // layer 0: g_xh [N,144] @ W0 -> g_hs -> g_act
    k_gemm_f16<<<gemm_grid, 256>>>(0, 0, N, K0P, K0P);
    k_aggregate<<<agg_grid, 256>>>(b0, nullptr, N);
    // layer 1
    k_gemm_f16<<<gemm_grid, 256>>>(1, 1, N, H, H);
    k_aggregate<<<agg_grid, 256>>>(b1, nullptr, N);
    // layer 2
    k_gemm_f16<<<gemm_grid, 256>>>(1, 2, N, H, H);
    k_aggregate<<<agg_grid, 256>>>(b2, nullptr, N);
    // layer 3 -> d_out (fp32)
    k_gemm_f16<<<gemm_grid, 256>>>(1, 3, N, H, H);
    k_aggregate<<<agg_grid, 256>>>(b3, out, N);
}